// round 15
// baseline (speedup 1.0000x reference)
#include <cuda_runtime.h>
#include <cuda_fp16.h>
#include <math.h>
#include <stdint.h>

#define NB 8
#define NS 1025
#define NE 1408
#define NH 16
#define ND 88
#define NM (NB*NS)      // 8200
#define DPAD 96
#define QKROW (NH*DPAD) // 1536
#define SVT 1088        // padded token dim for V^T
#define EE  (NE*NE)

// scale * log2(e), folded into Q at projection time
#define QSC (0.10660035817780521f * 1.4426950408889634f)

// Persistent scratch (zero-initialized; padding regions stay zero).
static __device__ __half g_ah[(size_t)NM * NE];
static __device__ __half g_wh[(size_t)4 * EE];
static __device__ __half g_ch[(size_t)NM * NE];
static __device__ __half g_qh[(size_t)NM * QKROW];
static __device__ __half g_kh[(size_t)NM * QKROW];
static __device__ __half g_vth[(size_t)NB * NH * DPAD * SVT];

// ===========================================================================
// Helpers
// ===========================================================================
__device__ __forceinline__ uint32_t smem_to_u32(const void* p) {
    uint32_t a;
    asm("{ .reg .u64 t; cvta.to.shared.u64 t, %1; cvt.u32.u64 %0, t; }"
        : "=r"(a) : "l"(p));
    return a;
}
__device__ __forceinline__ void ldsm_x4(uint32_t* r, uint32_t addr) {
    asm volatile("ldmatrix.sync.aligned.m8n8.x4.shared.b16 {%0,%1,%2,%3}, [%4];"
                 : "=r"(r[0]), "=r"(r[1]), "=r"(r[2]), "=r"(r[3]) : "r"(addr));
}
__device__ __forceinline__ void mma_f16(float* c, const uint32_t* a,
                                        const uint32_t* b) {
    asm volatile(
        "mma.sync.aligned.m16n8k16.row.col.f32.f16.f16.f32 "
        "{%0,%1,%2,%3}, {%4,%5,%6,%7}, {%8,%9}, {%0,%1,%2,%3};"
        : "+f"(c[0]), "+f"(c[1]), "+f"(c[2]), "+f"(c[3])
        : "r"(a[0]), "r"(a[1]), "r"(a[2]), "r"(a[3]), "r"(b[0]), "r"(b[1]));
}
__device__ __forceinline__ void cp16(uint32_t dst, const void* src) {
    asm volatile("cp.async.cg.shared.global [%0], [%1], 16;"
                 :: "r"(dst), "l"(__cvta_generic_to_global(src)));
}
#define CP_COMMIT() asm volatile("cp.async.commit_group;" ::: "memory")
#define CP_WAIT(n)  asm volatile("cp.async.wait_group %0;" :: "n"(n) : "memory")

__device__ __forceinline__ float ex2f(float x) {
    float y;
    asm("ex2.approx.f32 %0, %1;" : "=f"(y) : "f"(x));
    return y;
}

// ===========================================================================
// Prep kernels
// ===========================================================================
__global__ void tohalf_kernel(const float* __restrict__ in,
                              __half* __restrict__ hi, int n4)
{
    int i = blockIdx.x * blockDim.x + threadIdx.x;
    if (i >= n4) return;
    float4 x = ((const float4*)in)[i];
    union { __half2 h2[2]; uint2 u; } H;
    H.h2[0] = __floats2half2_rn(x.x, x.y);
    H.h2[1] = __floats2half2_rn(x.z, x.w);
    ((uint2*)hi)[i] = H.u;
}

__global__ void tohalf4_kernel(const float* __restrict__ w0,
                               const float* __restrict__ w1,
                               const float* __restrict__ w2,
                               const float* __restrict__ w3,
                               __half* __restrict__ hi, int n4)
{
    int i = blockIdx.x * blockDim.x + threadIdx.x;
    if (i >= n4) return;
    const int g = blockIdx.y;
    const float* in = (g == 0) ? w0 : (g == 1) ? w1 : (g == 2) ? w2 : w3;
    float4 x = ((const float4*)in)[i];
    union { __half2 h2[2]; uint2 u; } H;
    H.h2[0] = __floats2half2_rn(x.x, x.y);
    H.h2[1] = __floats2half2_rn(x.z, x.w);
    ((uint2*)hi)[(size_t)g * (EE / 4) + i] = H.u;
}

// ===========================================================================
// HMMA GEMM, fp16 single-term, persistent CTAs.
// CTA tile 128x128, 8 warps (2x4), warp tile 64x32, BK=64, cp.async 2-stage,
// one __syncthreads per chunk.
// ===========================================================================
#define GK      NE
#define BKC     64
#define NCHUNK  (GK / BKC)    // 22
#define SROW    72
#define SROWB   (SROW * 2)    // 144
#define MAT_BYTES   (128 * SROWB)          // 18432
#define STAGE_BYTES (2 * MAT_BYTES)        // 36864
#define GEMM_SMEM   (2 * STAGE_BYTES)      // 73728
#define PGRID   296                        // 2 CTAs/SM * 148 SMs
#define NT_QKV  (33 * 65)                  // 2145
#define NT_WO   (11 * 65)                  // 715

// Per-thread constants (tile-independent)
#define GEMM_TCONST \
    extern __shared__ char sm[]; \
    const uint32_t smemu = smem_to_u32(sm); \
    const int tid  = threadIdx.x; \
    const int wid  = tid >> 5; \
    const int lane = tid & 31; \
    const int wm = (wid >> 2) * 64; \
    const int wn = (wid & 3) * 32; \
    int rowL[4], chL[4]; \
    uint32_t soL[4]; \
    _Pragma("unroll") \
    for (int i = 0; i < 4; i++) { \
        int slot = tid + i * 256; \
        rowL[i] = slot >> 3; \
        chL[i]  = slot & 7; \
        soL[i] = (uint32_t)(rowL[i] * SROWB + chL[i] * 16); \
    } \
    const uint32_t aoff = \
        (uint32_t)((wm + ((lane >> 3) & 1) * 8 + (lane & 7)) * SROWB \
                   + (lane >> 4) * 16); \
    const uint32_t boff = \
        (uint32_t)((wn + ((lane >> 4) << 3) + (lane & 7)) * SROWB \
                   + ((lane >> 3) & 1) * 16);

#define GEMM_TILE_SETUP(Ah, Wh, bm, bn) \
    const char* aB[4]; \
    const char* wB[4]; \
    _Pragma("unroll") \
    for (int i = 0; i < 4; i++) { \
        int ga = bm + rowL[i]; \
        ga = (ga < NM) ? ga : (NM - 1); \
        aB[i] = (const char*)(Ah) + ((size_t)ga * GK + chL[i] * 8) * 2; \
        wB[i] = (const char*)(Wh) + ((size_t)((bn) + rowL[i]) * GK + chL[i] * 8) * 2; \
    } \
    float acc[4][4][4]; \
    _Pragma("unroll") \
    for (int mi = 0; mi < 4; mi++) \
        _Pragma("unroll") \
        for (int ni = 0; ni < 4; ni++) \
            _Pragma("unroll") \
            for (int j = 0; j < 4; j++) acc[mi][ni][j] = 0.f;

#define GEMM_LOAD(c_) do { \
    const uint32_t sb_ = smemu + ((c_) & 1) * STAGE_BYTES; \
    const uint32_t kb_ = (uint32_t)(c_) * (BKC * 2); \
    _Pragma("unroll") \
    for (int i_ = 0; i_ < 4; i_++) { \
        cp16(sb_ + soL[i_],             aB[i_] + kb_); \
        cp16(sb_ + MAT_BYTES + soL[i_], wB[i_] + kb_); \
    } \
} while (0)

// Single-sync pipeline: [wait(0); sync; load(c+1); compute(c)].
// Cross-tile: next tile's iter-0 sync orders every warp's last compute
// before any stage-1 overwrite; epilogue touches no smem; all cp.async
// groups drained at tile end.
#define GEMM_MAINLOOP \
    GEMM_LOAD(0); CP_COMMIT(); \
    _Pragma("unroll 1") \
    for (int c = 0; c < NCHUNK; c++) { \
        CP_WAIT(0); \
        __syncthreads(); \
        if (c + 1 < NCHUNK) { GEMM_LOAD(c + 1); CP_COMMIT(); } \
        const uint32_t base = smemu + (uint32_t)((c & 1) * STAGE_BYTES); \
        const uint32_t aHi = base; \
        const uint32_t bHi = base + MAT_BYTES; \
        _Pragma("unroll") \
        for (int ks = 0; ks < 4; ks++) { \
            const uint32_t ksb = ks * 32; \
            uint32_t ah[16], bh[8]; \
            _Pragma("unroll") \
            for (int mi = 0; mi < 4; mi++) \
                ldsm_x4(&ah[mi * 4], aHi + aoff + mi * 16 * SROWB + ksb); \
            ldsm_x4(&bh[0], bHi + boff + ksb); \
            ldsm_x4(&bh[4], bHi + boff + 16 * SROWB + ksb); \
            _Pragma("unroll") \
            for (int mi = 0; mi < 4; mi++) \
                _Pragma("unroll") \
                for (int ni = 0; ni < 4; ni++) \
                    mma_f16(acc[mi][ni], &ah[mi * 4], &bh[ni * 2]); \
        } \
    }

// Persistent fused QKV GEMM. Tile t: g = (t%33)/11, bn = ((t%33)%11)*128,
// bm = (t/33)*128.  g0->Q(RoPE,*QSC), g1->K(RoPE), g2->V^T.
__global__ __launch_bounds__(256, 2) void gemm_qkv_kernel(
    const float* __restrict__ bq, const float* __restrict__ bk,
    const float* __restrict__ bv,
    const float* __restrict__ rcos, const float* __restrict__ rsin)
{
    GEMM_TCONST

#pragma unroll 1
    for (int t = blockIdx.x; t < NT_QKV; t += PGRID) {
        const int tg = t % 33;
        const int g  = tg / 11;
        const int bn = (tg % 11) * 128;
        const int bm = (t / 33) * 128;
        const __half* Ah = g_ah;
        const __half* Wh = g_wh + (size_t)g * EE;
        const float* bias = (g == 0) ? bq : (g == 1) ? bk : bv;

        GEMM_TILE_SETUP(Ah, Wh, bm, bn)
        GEMM_MAINLOOP

        const int r0 = bm + wm + (lane >> 2);
        const int c0 = bn + wn + (lane & 3) * 2;
#pragma unroll
        for (int mi = 0; mi < 4; mi++) {
#pragma unroll
            for (int nt = 0; nt < 4; nt++) {
                const int gc = c0 + nt * 8;
                const float bx = bias[gc], by = bias[gc + 1];
                const int hh = gc / ND;
                const int dd = gc - hh * ND;
#pragma unroll
                for (int h2i = 0; h2i < 2; h2i++) {
                    const int gr = r0 + mi * 16 + h2i * 8;
                    if (gr >= NM) continue;
                    float xr = acc[mi][nt][2 * h2i + 0] + bx;
                    float xi = acc[mi][nt][2 * h2i + 1] + by;
                    if (g <= 1) {
                        const int st = gr % NS;
                        const float cc = rcos[st * (ND / 2) + (dd >> 1)];
                        const float ss = rsin[st * (ND / 2) + (dd >> 1)];
                        float orr = xr * cc - xi * ss;
                        float oii = xr * ss + xi * cc;
                        size_t off = (size_t)gr * QKROW + hh * DPAD + dd;
                        if (g == 0) {
                            *(__half2*)(g_qh + off) =
                                __floats2half2_rn(orr * QSC, oii * QSC);
                        } else {
                            *(__half2*)(g_kh + off) = __floats2half2_rn(orr, oii);
                        }
                    } else {
                        const int bb = gr / NS;
                        const int st = gr - bb * NS;
                        size_t base2 = ((size_t)((bb * NH + hh) * DPAD) + dd) * SVT + st;
                        g_vth[base2]       = __float2half_rn(xr);
                        g_vth[base2 + SVT] = __float2half_rn(xi);
                    }
                }
            }
        }
    }
}

// Persistent Wo GEMM (fp32 out). Tile t: bn = (t%11)*128, bm = (t/11)*128.
__global__ __launch_bounds__(256, 2) void gemm_wo_kernel(
    const float* __restrict__ bias, float* __restrict__ C)
{
    GEMM_TCONST

#pragma unroll 1
    for (int t = blockIdx.x; t < NT_WO; t += PGRID) {
        const int bn = (t % 11) * 128;
        const int bm = (t / 11) * 128;
        const __half* Ah = g_ch;
        const __half* Wh = g_wh + (size_t)3 * EE;

        GEMM_TILE_SETUP(Ah, Wh, bm, bn)
        GEMM_MAINLOOP

        const int r0 = bm + wm + (lane >> 2);
        const int c0 = bn + wn + (lane & 3) * 2;
#pragma unroll
        for (int mi = 0; mi < 4; mi++) {
#pragma unroll
            for (int nt = 0; nt < 4; nt++) {
                const int gc = c0 + nt * 8;
                const float bx = bias[gc], by = bias[gc + 1];
#pragma unroll
                for (int h2i = 0; h2i < 2; h2i++) {
                    const int gr = r0 + mi * 16 + h2i * 8;
                    if (gr >= NM) continue;
                    float xr = acc[mi][nt][2 * h2i + 0] + bx;
                    float xi = acc[mi][nt][2 * h2i + 1] + by;
                    *(float2*)(C + (size_t)gr * NE + gc) = make_float2(xr, xi);
                }
            }
        }
    }
}

// ===========================================================================
// HMMA flash attention — R14 structure + affine prefetch addressing.
// exp2-domain softmax (Q pre-scaled), P via smem, single-sync KV pipeline.
// BQ=64, BK=64, 4 warps, 3 CTAs/SM, K+V double-buffered.
// ===========================================================================
#define KSTB 208
#define VSTB 144
#define KVSTAGE_B 27136                  // 64*208 + 96*144
#define OFF_V_IN_STAGE 13312
#define OFF_PH (2 * KVSTAGE_B)           // 54272
#define ATT_SMEM (OFF_PH + 64 * VSTB)    // 63488

__global__ __launch_bounds__(128, 3) void attn_hmma_kernel()
{
    extern __shared__ char sm[];
    const uint32_t smemu = smem_to_u32(sm);
    const int tid  = threadIdx.x;
    const int wid  = tid >> 5;
    const int lane = tid & 31;
    const int wm   = wid * 16;

    const int qt = blockIdx.x, h = blockIdx.y, b = blockIdx.z;
    const int q0 = qt * 64;

    const char* qh_base = (const char*)(g_qh + (size_t)b * NS * QKROW + h * DPAD);
    const char* kh_base = (const char*)(g_kh + (size_t)b * NS * QKROW + h * DPAD);
    const char* vh_base = (const char*)(g_vth + (size_t)(b * NH + h) * DPAD * SVT);

    // affine load assignment:
    //  K/Q: row rk = tid>>1 (0..63), chunks ch0..ch0+5 (ch0 = (tid&1)*6)
    //  V:   rows rv0+16j (rv0 = tid>>3, j<6), chunk cv = tid&7
    const int rk  = tid >> 1;
    const int ch0 = (tid & 1) * 6;
    const int rv0 = tid >> 3;
    const int cv  = tid & 7;
    const uint32_t kdoff = (uint32_t)(rk * KSTB + ch0 * 16);
    const uint32_t vdoff = (uint32_t)(OFF_V_IN_STAGE + rv0 * VSTB + cv * 16);
    const char* vsrc0 = vh_base + (size_t)rv0 * (SVT * 2) + cv * 16;

    // ---- stage Q via stage-0 K buffer, build register fragments ----
    {
        int tok = q0 + rk; if (tok > NS - 1) tok = NS - 1;
        const char* src = qh_base + (size_t)tok * (QKROW * 2) + ch0 * 16;
#pragma unroll
        for (int j = 0; j < 6; j++) cp16(smemu + kdoff + j * 16, src + j * 16);
    }
    CP_COMMIT(); CP_WAIT(0);
    __syncthreads();

    const uint32_t aoffQ = (uint32_t)((wm + ((lane >> 3) & 1) * 8 + (lane & 7)) * KSTB
                                      + (lane >> 4) * 16);
    uint32_t qhf[6][4];
#pragma unroll
    for (int ks = 0; ks < 6; ks++)
        ldsm_x4(qhf[ks], smemu + aoffQ + ks * 32);
    __syncthreads();

    // ---- preload K+V (kt=0) into stage 0 ----
    {
        const char* ksrc = kh_base + (size_t)rk * (QKROW * 2) + ch0 * 16;
#pragma unroll
        for (int j = 0; j < 6; j++) cp16(smemu + kdoff + j * 16, ksrc + j * 16);
#pragma unroll
        for (int j = 0; j < 6; j++)
            cp16(smemu + vdoff + j * 16 * VSTB, vsrc0 + (size_t)j * 16 * (SVT * 2));
    }
    CP_COMMIT();

    float acc_o[11][4];
#pragma unroll
    for (int nt = 0; nt < 11; nt++)
#pragma unroll
        for (int j = 0; j < 4; j++) acc_o[nt][j] = 0.f;
    float mrun[2] = {-INFINITY, -INFINITY};
    float lrun[2] = {0.f, 0.f};

    const uint32_t kboff = (uint32_t)((((lane >> 4) << 3) + (lane & 7)) * KSTB
                                      + ((lane >> 3) & 1) * 16);
    const uint32_t vboff = (uint32_t)((((lane >> 4) << 3) + (lane & 7)) * VSTB
                                      + ((lane >> 3) & 1) * 16);
    const uint32_t apoff = (uint32_t)((wm + ((lane >> 3) & 1) * 8 + (lane & 7)) * VSTB
                                      + (lane >> 4) * 16);
    const int colb = (lane & 3) * 2;
    const int prow_lo = wm + (lane >> 2);

#pragma unroll 1
    for (int kt = 0; kt < 17; kt++) {
        const int k0 = kt * 64;

        // wait for K+V(kt), single barrier, then prefetch(kt+1)
        CP_WAIT(0);
        __syncthreads();

        if (kt + 1 < 17) {
            const uint32_t snx = smemu + ((kt + 1) & 1) * KVSTAGE_B;
            const int kn0 = (kt + 1) * 64;
            int tok = kn0 + rk; if (tok > NS - 1) tok = NS - 1;
            const char* ksrc = kh_base + (size_t)tok * (QKROW * 2) + ch0 * 16;
#pragma unroll
            for (int j = 0; j < 6; j++) cp16(snx + kdoff + j * 16, ksrc + j * 16);
            const char* vsrc = vsrc0 + kn0 * 2;
#pragma unroll
            for (int j = 0; j < 6; j++)
                cp16(snx + vdoff + j * 16 * VSTB, vsrc + (size_t)j * 16 * (SVT * 2));
            CP_COMMIT();
        }

        const uint32_t scur = smemu + (kt & 1) * KVSTAGE_B;

        // ---- S = Q K^T (log2 domain) ----
        float sacc[8][4];
#pragma unroll
        for (int nt = 0; nt < 8; nt++)
#pragma unroll
            for (int j = 0; j < 4; j++) sacc[nt][j] = 0.f;

#pragma unroll
        for (int ks = 0; ks < 6; ks++) {
            uint32_t kbh[16];
#pragma unroll
            for (int j = 0; j < 4; j++)
                ldsm_x4(&kbh[j * 4], scur + kboff + j * 16 * KSTB + ks * 32);
#pragma unroll
            for (int nt = 0; nt < 8; nt++)
                mma_f16(sacc[nt], qhf[ks], &kbh[nt * 2]);
        }

        if (k0 + 64 > NS) {
#pragma unroll
            for (int nt = 0; nt < 8; nt++)
#pragma unroll
                for (int j = 0; j < 4; j++) {
                    int col = k0 + nt * 8 + colb + (j & 1);
                    if (col >= NS) sacc[nt][j] = -INFINITY;
                }
        }

        // ---- online softmax (exp2 domain) ----
        float ml0 = -INFINITY, ml1 = -INFINITY;
#pragma unroll
        for (int nt = 0; nt < 8; nt++) {
            ml0 = fmaxf(ml0, fmaxf(sacc[nt][0], sacc[nt][1]));
            ml1 = fmaxf(ml1, fmaxf(sacc[nt][2], sacc[nt][3]));
        }
        ml0 = fmaxf(ml0, __shfl_xor_sync(0xffffffffu, ml0, 1));
        ml0 = fmaxf(ml0, __shfl_xor_sync(0xffffffffu, ml0, 2));
        ml1 = fmaxf(ml1, __shfl_xor_sync(0xffffffffu, ml1, 1));
        ml1 = fmaxf(ml1, __shfl_xor_sync(0xffffffffu, ml1, 2));

        float mn0 = fmaxf(mrun[0], ml0), mn1 = fmaxf(mrun[1], ml1);
        float al0 = ex2f(mrun[0] - mn0), al1 = ex2f(mrun[1] - mn1);
        mrun[0] = mn0; mrun[1] = mn1;

        float rs0 = 0.f, rs1 = 0.f;
#pragma unroll
        for (int nt = 0; nt < 8; nt++) {
            float p00 = ex2f(sacc[nt][0] - mn0);
            float p01 = ex2f(sacc[nt][1] - mn0);
            float p10 = ex2f(sacc[nt][2] - mn1);
            float p11 = ex2f(sacc[nt][3] - mn1);
            rs0 += p00 + p01;
            rs1 += p10 + p11;
            uint32_t po = (uint32_t)(prow_lo * VSTB + (nt * 8 + colb) * 2);
            *(__half2*)(sm + OFF_PH + po) = __floats2half2_rn(p00, p01);
            *(__half2*)(sm + OFF_PH + po + 8 * VSTB) = __floats2half2_rn(p10, p11);
        }
        rs0 += __shfl_xor_sync(0xffffffffu, rs0, 1);
        rs0 += __shfl_xor_sync(0xffffffffu, rs0, 2);
        rs1 += __shfl_xor_sync(0xffffffffu, rs1, 1);
        rs1 += __shfl_xor_sync(0xffffffffu, rs1, 2);
        lrun[0] = lrun[0] * al0 + rs0;
        lrun[1] = lrun[1] * al1 + rs1;

#pragma unroll
        for (int nt = 0; nt < 11; nt++) {
            acc_o[nt][0] *= al0; acc_o[nt][1] *= al0;
            acc_o[nt][2] *= al1; acc_o[nt][3] *= al1;
        }
        __syncwarp();   // P rows per-warp private; warp-local STS->ldsm ordering

        // ---- O += P V ----
#pragma unroll
        for (int ks = 0; ks < 4; ks++) {
            uint32_t aph[4];
            ldsm_x4(aph, smemu + OFF_PH + apoff + ks * 32);
            uint32_t vbh[24];
#pragma unroll
            for (int j = 0; j < 6; j++)
                ldsm_x4(&vbh[j * 4],
                        scur + OFF_V_IN_STAGE + vboff + j * 16 * VSTB + ks * 32);
#pragma unroll
            for (int nt = 0; nt < 11; nt++)
                mma_f16(acc_o[nt], aph, &vbh[nt * 2]);
        }
        // no trailing sync: next iteration's top sync covers the stage hazard
    }

    // ---- epilogue: ctx as fp16 (feeds Wo GEMM) ----
    const float inv0 = 1.f / lrun[0];
    const float inv1 = 1.f / lrun[1];
    const int gq0 = q0 + wm + (lane >> 2);
    const int gq1 = gq0 + 8;
    const size_t ob = (size_t)b * NS * NE + (size_t)h * ND;
#pragma unroll
    for (int nt = 0; nt < 11; nt++) {
        int col = nt * 8 + colb;
        if (gq0 < NS) {
            *(__half2*)(g_ch + ob + (size_t)gq0 * NE + col) =
                __floats2half2_rn(acc_o[nt][0] * inv0, acc_o[nt][1] * inv0);
        }
        if (gq1 < NS) {
            *(__half2*)(g_ch + ob + (size_t)gq1 * NE + col) =
                __floats2half2_rn(acc_o[nt][2] * inv1, acc_o[nt][3] * inv1);
        }
    }
}

// ---------------------------------------------------------------------------
// Launch
// ---------------------------------------------------------------------------
extern "C" void kernel_launch(void* const* d_in, const int* in_sizes, int n_in,
                              void* d_out, int out_size)
{
    const float* hidden = (const float*)d_in[0];
    const float* fcos   = (const float*)d_in[1];
    const float* fsin   = (const float*)d_in[2];
    const float* Wq     = (const float*)d_in[3];
    const float* bq     = (const float*)d_in[4];
    const float* Wk     = (const float*)d_in[5];
    const float* bk     = (const float*)d_in[6];
    const float* Wv     = (const float*)d_in[7];
    const float* bv     = (const float*)d_in[8];
    const float* Wo     = (const float*)d_in[9];
    const float* bo     = (const float*)d_in[10];
    float* out = (float*)d_out;

    __half *ah, *wh;
    cudaGetSymbolAddress((void**)&ah, g_ah);
    cudaGetSymbolAddress((void**)&wh, g_wh);

    static int smem_set = 0;
    if (!smem_set) {
        cudaFuncSetAttribute(gemm_qkv_kernel,
                             cudaFuncAttributeMaxDynamicSharedMemorySize, GEMM_SMEM);
        cudaFuncSetAttribute(gemm_wo_kernel,
                             cudaFuncAttributeMaxDynamicSharedMemorySize, GEMM_SMEM);
        cudaFuncSetAttribute(attn_hmma_kernel,
                             cudaFuncAttributeMaxDynamicSharedMemorySize, ATT_SMEM);
        smem_set = 1;
    }

    // ---- prep ----
    const int nA4 = NM * NE / 4;
    const int nW4 = EE / 4;
    tohalf_kernel<<<(nA4 + 255) / 256, 256>>>(hidden, ah, nA4);
    dim3 sgrid((nW4 + 255) / 256, 4);
    tohalf4_kernel<<<sgrid, 256>>>(Wq, Wk, Wv, Wo, wh, nW4);

    // ---- fused QKV projections (+RoPE, +V transpose), persistent ----
    gemm_qkv_kernel<<<PGRID, 256, GEMM_SMEM>>>(bq, bk, bv, fcos, fsin);

    // ---- attention ----
    dim3 attn_grid(17, NH, NB);
    attn_hmma_kernel<<<attn_grid, 128, ATT_SMEM>>>();

    // ---- output projection, persistent ----
    gemm_wo_kernel<<<PGRID, 256, GEMM_SMEM>>>(bo, out);
}

// round 17
// speedup vs baseline: 1.2013x; 1.2013x over previous
#include <cuda_runtime.h>
#include <cuda_fp16.h>
#include <math.h>
#include <stdint.h>

#define NB 8
#define NS 1025
#define NE 1408
#define NH 16
#define ND 88
#define NM (NB*NS)      // 8200
#define DPAD 96
#define QKROW (NH*DPAD) // 1536
#define SVT 1088        // padded token dim for V^T
#define EE  (NE*NE)

// scale * log2(e), folded into Q at projection time
#define QSC (0.10660035817780521f * 1.4426950408889634f)

// Persistent scratch (zero-initialized; padding regions stay zero).
static __device__ __half g_ah[(size_t)NM * NE];
static __device__ __half g_wh[(size_t)4 * EE];
static __device__ __half g_ch[(size_t)NM * NE];
static __device__ __half g_qh[(size_t)NM * QKROW];
static __device__ __half g_kh[(size_t)NM * QKROW];
static __device__ __half g_vth[(size_t)NB * NH * DPAD * SVT];

// ===========================================================================
// Helpers
// ===========================================================================
__device__ __forceinline__ uint32_t smem_to_u32(const void* p) {
    uint32_t a;
    asm("{ .reg .u64 t; cvta.to.shared.u64 t, %1; cvt.u32.u64 %0, t; }"
        : "=r"(a) : "l"(p));
    return a;
}
__device__ __forceinline__ void ldsm_x4(uint32_t* r, uint32_t addr) {
    asm volatile("ldmatrix.sync.aligned.m8n8.x4.shared.b16 {%0,%1,%2,%3}, [%4];"
                 : "=r"(r[0]), "=r"(r[1]), "=r"(r[2]), "=r"(r[3]) : "r"(addr));
}
__device__ __forceinline__ void mma_f16(float* c, const uint32_t* a,
                                        const uint32_t* b) {
    asm volatile(
        "mma.sync.aligned.m16n8k16.row.col.f32.f16.f16.f32 "
        "{%0,%1,%2,%3}, {%4,%5,%6,%7}, {%8,%9}, {%0,%1,%2,%3};"
        : "+f"(c[0]), "+f"(c[1]), "+f"(c[2]), "+f"(c[3])
        : "r"(a[0]), "r"(a[1]), "r"(a[2]), "r"(a[3]), "r"(b[0]), "r"(b[1]));
}
__device__ __forceinline__ void cp16(uint32_t dst, const void* src) {
    asm volatile("cp.async.cg.shared.global [%0], [%1], 16;"
                 :: "r"(dst), "l"(__cvta_generic_to_global(src)));
}
#define CP_COMMIT() asm volatile("cp.async.commit_group;" ::: "memory")
#define CP_WAIT(n)  asm volatile("cp.async.wait_group %0;" :: "n"(n) : "memory")

__device__ __forceinline__ float ex2f(float x) {
    float y;
    asm("ex2.approx.f32 %0, %1;" : "=f"(y) : "f"(x));
    return y;
}

// ===========================================================================
// Prep kernels
// ===========================================================================
__global__ void tohalf_kernel(const float* __restrict__ in,
                              __half* __restrict__ hi, int n4)
{
    int i = blockIdx.x * blockDim.x + threadIdx.x;
    if (i >= n4) return;
    float4 x = ((const float4*)in)[i];
    union { __half2 h2[2]; uint2 u; } H;
    H.h2[0] = __floats2half2_rn(x.x, x.y);
    H.h2[1] = __floats2half2_rn(x.z, x.w);
    ((uint2*)hi)[i] = H.u;
}

__global__ void tohalf4_kernel(const float* __restrict__ w0,
                               const float* __restrict__ w1,
                               const float* __restrict__ w2,
                               const float* __restrict__ w3,
                               __half* __restrict__ hi, int n4)
{
    int i = blockIdx.x * blockDim.x + threadIdx.x;
    if (i >= n4) return;
    const int g = blockIdx.y;
    const float* in = (g == 0) ? w0 : (g == 1) ? w1 : (g == 2) ? w2 : w3;
    float4 x = ((const float4*)in)[i];
    union { __half2 h2[2]; uint2 u; } H;
    H.h2[0] = __floats2half2_rn(x.x, x.y);
    H.h2[1] = __floats2half2_rn(x.z, x.w);
    ((uint2*)hi)[(size_t)g * (EE / 4) + i] = H.u;
}

// ===========================================================================
// HMMA GEMM (R14 form): fp16 single-term, CTA 128x128, 8 warps (2x4),
// warp tile 64x32, BK=64, cp.async 2-stage, one __syncthreads per chunk.
// ===========================================================================
#define GK      NE
#define BKC     64
#define NCHUNK  (GK / BKC)    // 22
#define SROW    72
#define SROWB   (SROW * 2)    // 144
#define MAT_BYTES   (128 * SROWB)          // 18432
#define STAGE_BYTES (2 * MAT_BYTES)        // 36864
#define GEMM_SMEM   (2 * STAGE_BYTES)      // 73728

#define GEMM_PROLOG \
    extern __shared__ char sm[]; \
    const uint32_t smemu = smem_to_u32(sm); \
    const int tid  = threadIdx.x; \
    const int wid  = tid >> 5; \
    const int lane = tid & 31; \
    const int bm = blockIdx.y * 128; \
    const int wm = (wid >> 2) * 64; \
    const int wn = (wid & 3) * 32; \
    uint32_t soL[4]; \
    const char* aB[4]; \
    const char* wB[4]; \
    _Pragma("unroll") \
    for (int i = 0; i < 4; i++) { \
        int slot = tid + i * 256; \
        int row = slot >> 3; \
        int ch  = slot & 7; \
        int ga = bm + row; \
        ga = (ga < NM) ? ga : (NM - 1); \
        soL[i] = (uint32_t)(row * SROWB + ch * 16); \
        aB[i] = (const char*)Ah + ((size_t)ga * GK + ch * 8) * 2; \
        wB[i] = (const char*)Wh + ((size_t)(bn + row) * GK + ch * 8) * 2; \
    } \
    const uint32_t aoff = \
        (uint32_t)((wm + ((lane >> 3) & 1) * 8 + (lane & 7)) * SROWB \
                   + (lane >> 4) * 16); \
    const uint32_t boff = \
        (uint32_t)((wn + ((lane >> 4) << 3) + (lane & 7)) * SROWB \
                   + ((lane >> 3) & 1) * 16); \
    float acc[4][4][4]; \
    _Pragma("unroll") \
    for (int mi = 0; mi < 4; mi++) \
        _Pragma("unroll") \
        for (int ni = 0; ni < 4; ni++) \
            _Pragma("unroll") \
            for (int j = 0; j < 4; j++) acc[mi][ni][j] = 0.f;

#define GEMM_LOAD(c_) do { \
    const uint32_t sb_ = smemu + ((c_) & 1) * STAGE_BYTES; \
    const uint32_t kb_ = (uint32_t)(c_) * (BKC * 2); \
    _Pragma("unroll") \
    for (int i_ = 0; i_ < 4; i_++) { \
        cp16(sb_ + soL[i_],             aB[i_] + kb_); \
        cp16(sb_ + MAT_BYTES + soL[i_], wB[i_] + kb_); \
    } \
} while (0)

// Single-sync pipeline: [wait(0); sync; load(c+1); compute(c)]
#define GEMM_MAINLOOP \
    GEMM_LOAD(0); CP_COMMIT(); \
    _Pragma("unroll 1") \
    for (int c = 0; c < NCHUNK; c++) { \
        CP_WAIT(0); \
        __syncthreads(); \
        if (c + 1 < NCHUNK) { GEMM_LOAD(c + 1); CP_COMMIT(); } \
        const uint32_t base = smemu + (uint32_t)((c & 1) * STAGE_BYTES); \
        const uint32_t aHi = base; \
        const uint32_t bHi = base + MAT_BYTES; \
        _Pragma("unroll") \
        for (int ks = 0; ks < 4; ks++) { \
            const uint32_t ksb = ks * 32; \
            uint32_t ah[16], bh[8]; \
            _Pragma("unroll") \
            for (int mi = 0; mi < 4; mi++) \
                ldsm_x4(&ah[mi * 4], aHi + aoff + mi * 16 * SROWB + ksb); \
            ldsm_x4(&bh[0], bHi + boff + ksb); \
            ldsm_x4(&bh[4], bHi + boff + 16 * SROWB + ksb); \
            _Pragma("unroll") \
            for (int mi = 0; mi < 4; mi++) \
                _Pragma("unroll") \
                for (int ni = 0; ni < 4; ni++) \
                    mma_f16(acc[mi][ni], &ah[mi * 4], &bh[ni * 2]); \
        } \
    }

// Fused QKV GEMM: grid.x = 33 (g = bx/11): g0->Q(RoPE,*QSC), g1->K(RoPE), g2->V^T
__global__ __launch_bounds__(256, 2) void gemm_qkv_kernel(
    const float* __restrict__ bq, const float* __restrict__ bk,
    const float* __restrict__ bv,
    const float* __restrict__ rcos, const float* __restrict__ rsin)
{
    const int g  = blockIdx.x / 11;
    const int bn = (blockIdx.x % 11) * 128;
    const __half* Ah = g_ah;
    const __half* Wh = g_wh + (size_t)g * EE;
    const float* bias = (g == 0) ? bq : (g == 1) ? bk : bv;

    GEMM_PROLOG
    GEMM_MAINLOOP

    const int r0 = bm + wm + (lane >> 2);
    const int c0 = bn + wn + (lane & 3) * 2;
#pragma unroll
    for (int mi = 0; mi < 4; mi++) {
#pragma unroll
        for (int nt = 0; nt < 4; nt++) {
            const int gc = c0 + nt * 8;
            const float bx = bias[gc], by = bias[gc + 1];
            const int hh = gc / ND;
            const int dd = gc - hh * ND;
#pragma unroll
            for (int h2i = 0; h2i < 2; h2i++) {
                const int gr = r0 + mi * 16 + h2i * 8;
                if (gr >= NM) continue;
                float xr = acc[mi][nt][2 * h2i + 0] + bx;
                float xi = acc[mi][nt][2 * h2i + 1] + by;
                if (g <= 1) {
                    const int st = gr % NS;
                    const float cc = rcos[st * (ND / 2) + (dd >> 1)];
                    const float ss = rsin[st * (ND / 2) + (dd >> 1)];
                    float orr = xr * cc - xi * ss;
                    float oii = xr * ss + xi * cc;
                    size_t off = (size_t)gr * QKROW + hh * DPAD + dd;
                    if (g == 0) {
                        *(__half2*)(g_qh + off) =
                            __floats2half2_rn(orr * QSC, oii * QSC);
                    } else {
                        *(__half2*)(g_kh + off) = __floats2half2_rn(orr, oii);
                    }
                } else {
                    const int bb = gr / NS;
                    const int st = gr - bb * NS;
                    size_t base2 = ((size_t)((bb * NH + hh) * DPAD) + dd) * SVT + st;
                    g_vth[base2]       = __float2half_rn(xr);
                    g_vth[base2 + SVT] = __float2half_rn(xi);
                }
            }
        }
    }
}

// Wo GEMM (fp32 out)
__global__ __launch_bounds__(256, 2) void gemm_wo_kernel(
    const float* __restrict__ bias, float* __restrict__ C)
{
    const int bn = blockIdx.x * 128;
    const __half* Ah = g_ch;
    const __half* Wh = g_wh + (size_t)3 * EE;

    GEMM_PROLOG
    GEMM_MAINLOOP

    const int r0 = bm + wm + (lane >> 2);
    const int c0 = bn + wn + (lane & 3) * 2;
#pragma unroll
    for (int mi = 0; mi < 4; mi++) {
#pragma unroll
        for (int nt = 0; nt < 4; nt++) {
            const int gc = c0 + nt * 8;
            const float bx = bias[gc], by = bias[gc + 1];
#pragma unroll
            for (int h2i = 0; h2i < 2; h2i++) {
                const int gr = r0 + mi * 16 + h2i * 8;
                if (gr >= NM) continue;
                float xr = acc[mi][nt][2 * h2i + 0] + bx;
                float xi = acc[mi][nt][2 * h2i + 1] + by;
                *(float2*)(C + (size_t)gr * NE + gc) = make_float2(xr, xi);
            }
        }
    }
}

// ===========================================================================
// HMMA flash attention — R14 structure, BQ=96 (6 warps, 192 threads).
// exp2-domain softmax, P via smem, div/mod prefetch (coalesced),
// single-sync KV double-buffered pipeline, 2 CTAs/SM (12 warps/SM).
// ===========================================================================
#define BQT 96
#define ATT_THREADS 192
#define KSTB 208
#define VSTB 144
#define KVSTAGE_B 27136                  // 64*208 + 96*144
#define OFF_V_IN_STAGE 13312
#define OFF_PH (2 * KVSTAGE_B)           // 54272
#define ATT_SMEM (OFF_PH + BQT * VSTB)   // 54272 + 13824 = 68096

__global__ __launch_bounds__(ATT_THREADS, 2) void attn_hmma_kernel()
{
    extern __shared__ char sm[];
    const uint32_t smemu = smem_to_u32(sm);
    const int tid  = threadIdx.x;
    const int wid  = tid >> 5;
    const int lane = tid & 31;
    const int wm   = wid * 16;

    const int qt = blockIdx.x, h = blockIdx.y, b = blockIdx.z;
    const int q0 = qt * BQT;

    const char* qh_base = (const char*)(g_qh + (size_t)b * NS * QKROW + h * DPAD);
    const char* kh_base = (const char*)(g_kh + (size_t)b * NS * QKROW + h * DPAD);
    const char* vh_base = (const char*)(g_vth + (size_t)(b * NH + h) * DPAD * SVT);

    // ---- stage Q (96 rows x 12 ch) at smem base, build register fragments ----
    for (int i = tid; i < BQT * 12; i += ATT_THREADS) {
        int row = i / 12, ch = i % 12;
        int tok = q0 + row; if (tok > NS - 1) tok = NS - 1;
        cp16(smemu + row * KSTB + ch * 16,
             qh_base + (size_t)tok * (QKROW * 2) + ch * 16);
    }
    CP_COMMIT(); CP_WAIT(0);
    __syncthreads();

    const uint32_t aoffQ = (uint32_t)((wm + ((lane >> 3) & 1) * 8 + (lane & 7)) * KSTB
                                      + (lane >> 4) * 16);
    uint32_t qhf[6][4];
#pragma unroll
    for (int ks = 0; ks < 6; ks++)
        ldsm_x4(qhf[ks], smemu + aoffQ + ks * 32);
    __syncthreads();

    // ---- preload K+V (kt=0) into stage 0 ----
    for (int i = tid; i < 1536; i += ATT_THREADS) {
        if (i < 768) {
            int rk = i / 12, ck = i % 12;
            cp16(smemu + rk * KSTB + ck * 16,
                 kh_base + (size_t)rk * (QKROW * 2) + ck * 16);
        } else {
            int j = i - 768;
            int rv = j / 8, cv = j % 8;
            cp16(smemu + OFF_V_IN_STAGE + rv * VSTB + cv * 16,
                 vh_base + (size_t)rv * (SVT * 2) + cv * 16);
        }
    }
    CP_COMMIT();

    float acc_o[11][4];
#pragma unroll
    for (int nt = 0; nt < 11; nt++)
#pragma unroll
        for (int j = 0; j < 4; j++) acc_o[nt][j] = 0.f;
    float mrun[2] = {-INFINITY, -INFINITY};
    float lrun[2] = {0.f, 0.f};

    const uint32_t kboff = (uint32_t)((((lane >> 4) << 3) + (lane & 7)) * KSTB
                                      + ((lane >> 3) & 1) * 16);
    const uint32_t vboff = (uint32_t)((((lane >> 4) << 3) + (lane & 7)) * VSTB
                                      + ((lane >> 3) & 1) * 16);
    const uint32_t apoff = (uint32_t)((wm + ((lane >> 3) & 1) * 8 + (lane & 7)) * VSTB
                                      + (lane >> 4) * 16);
    const int colb = (lane & 3) * 2;
    const int prow_lo = wm + (lane >> 2);

#pragma unroll 1
    for (int kt = 0; kt < 17; kt++) {
        const int k0 = kt * 64;

        // wait for K+V(kt), single barrier, then prefetch(kt+1)
        CP_WAIT(0);
        __syncthreads();

        if (kt + 1 < 17) {
            const uint32_t snx = smemu + ((kt + 1) & 1) * KVSTAGE_B;
            const int kn0 = (kt + 1) * 64;
            for (int i = tid; i < 1536; i += ATT_THREADS) {
                if (i < 768) {
                    int rk = i / 12, ck = i % 12;
                    int tok = kn0 + rk; if (tok > NS - 1) tok = NS - 1;
                    cp16(snx + rk * KSTB + ck * 16,
                         kh_base + (size_t)tok * (QKROW * 2) + ck * 16);
                } else {
                    int j = i - 768;
                    int rv = j / 8, cv = j % 8;
                    cp16(snx + OFF_V_IN_STAGE + rv * VSTB + cv * 16,
                         vh_base + (size_t)rv * (SVT * 2) + kn0 * 2 + cv * 16);
                }
            }
            CP_COMMIT();
        }

        const uint32_t scur = smemu + (kt & 1) * KVSTAGE_B;

        // ---- S = Q K^T (log2 domain) ----
        float sacc[8][4];
#pragma unroll
        for (int nt = 0; nt < 8; nt++)
#pragma unroll
            for (int j = 0; j < 4; j++) sacc[nt][j] = 0.f;

#pragma unroll
        for (int ks = 0; ks < 6; ks++) {
            uint32_t kbh[16];
#pragma unroll
            for (int j = 0; j < 4; j++)
                ldsm_x4(&kbh[j * 4], scur + kboff + j * 16 * KSTB + ks * 32);
#pragma unroll
            for (int nt = 0; nt < 8; nt++)
                mma_f16(sacc[nt], qhf[ks], &kbh[nt * 2]);
        }

        if (k0 + 64 > NS) {
#pragma unroll
            for (int nt = 0; nt < 8; nt++)
#pragma unroll
                for (int j = 0; j < 4; j++) {
                    int col = k0 + nt * 8 + colb + (j & 1);
                    if (col >= NS) sacc[nt][j] = -INFINITY;
                }
        }

        // ---- online softmax (exp2 domain) ----
        float ml0 = -INFINITY, ml1 = -INFINITY;
#pragma unroll
        for (int nt = 0; nt < 8; nt++) {
            ml0 = fmaxf(ml0, fmaxf(sacc[nt][0], sacc[nt][1]));
            ml1 = fmaxf(ml1, fmaxf(sacc[nt][2], sacc[nt][3]));
        }
        ml0 = fmaxf(ml0, __shfl_xor_sync(0xffffffffu, ml0, 1));
        ml0 = fmaxf(ml0, __shfl_xor_sync(0xffffffffu, ml0, 2));
        ml1 = fmaxf(ml1, __shfl_xor_sync(0xffffffffu, ml1, 1));
        ml1 = fmaxf(ml1, __shfl_xor_sync(0xffffffffu, ml1, 2));

        float mn0 = fmaxf(mrun[0], ml0), mn1 = fmaxf(mrun[1], ml1);
        float al0 = ex2f(mrun[0] - mn0), al1 = ex2f(mrun[1] - mn1);
        mrun[0] = mn0; mrun[1] = mn1;

        float rs0 = 0.f, rs1 = 0.f;
#pragma unroll
        for (int nt = 0; nt < 8; nt++) {
            float p00 = ex2f(sacc[nt][0] - mn0);
            float p01 = ex2f(sacc[nt][1] - mn0);
            float p10 = ex2f(sacc[nt][2] - mn1);
            float p11 = ex2f(sacc[nt][3] - mn1);
            rs0 += p00 + p01;
            rs1 += p10 + p11;
            uint32_t po = (uint32_t)(prow_lo * VSTB + (nt * 8 + colb) * 2);
            *(__half2*)(sm + OFF_PH + po) = __floats2half2_rn(p00, p01);
            *(__half2*)(sm + OFF_PH + po + 8 * VSTB) = __floats2half2_rn(p10, p11);
        }
        rs0 += __shfl_xor_sync(0xffffffffu, rs0, 1);
        rs0 += __shfl_xor_sync(0xffffffffu, rs0, 2);
        rs1 += __shfl_xor_sync(0xffffffffu, rs1, 1);
        rs1 += __shfl_xor_sync(0xffffffffu, rs1, 2);
        lrun[0] = lrun[0] * al0 + rs0;
        lrun[1] = lrun[1] * al1 + rs1;

#pragma unroll
        for (int nt = 0; nt < 11; nt++) {
            acc_o[nt][0] *= al0; acc_o[nt][1] *= al0;
            acc_o[nt][2] *= al1; acc_o[nt][3] *= al1;
        }
        __syncwarp();   // P rows per-warp private; warp-local STS->ldsm ordering

        // ---- O += P V ----
#pragma unroll
        for (int ks = 0; ks < 4; ks++) {
            uint32_t aph[4];
            ldsm_x4(aph, smemu + OFF_PH + apoff + ks * 32);
            uint32_t vbh[24];
#pragma unroll
            for (int j = 0; j < 6; j++)
                ldsm_x4(&vbh[j * 4],
                        scur + OFF_V_IN_STAGE + vboff + j * 16 * VSTB + ks * 32);
#pragma unroll
            for (int nt = 0; nt < 11; nt++)
                mma_f16(acc_o[nt], aph, &vbh[nt * 2]);
        }
        // no trailing sync: next iteration's top sync covers the stage hazard
    }

    // ---- epilogue: ctx as fp16 (feeds Wo GEMM) ----
    const float inv0 = 1.f / lrun[0];
    const float inv1 = 1.f / lrun[1];
    const int gq0 = q0 + wm + (lane >> 2);
    const int gq1 = gq0 + 8;
    const size_t ob = (size_t)b * NS * NE + (size_t)h * ND;
#pragma unroll
    for (int nt = 0; nt < 11; nt++) {
        int col = nt * 8 + colb;
        if (gq0 < NS) {
            *(__half2*)(g_ch + ob + (size_t)gq0 * NE + col) =
                __floats2half2_rn(acc_o[nt][0] * inv0, acc_o[nt][1] * inv0);
        }
        if (gq1 < NS) {
            *(__half2*)(g_ch + ob + (size_t)gq1 * NE + col) =
                __floats2half2_rn(acc_o[nt][2] * inv1, acc_o[nt][3] * inv1);
        }
    }
}

// ---------------------------------------------------------------------------
// Launch
// ---------------------------------------------------------------------------
extern "C" void kernel_launch(void* const* d_in, const int* in_sizes, int n_in,
                              void* d_out, int out_size)
{
    const float* hidden = (const float*)d_in[0];
    const float* fcos   = (const float*)d_in[1];
    const float* fsin   = (const float*)d_in[2];
    const float* Wq     = (const float*)d_in[3];
    const float* bq     = (const float*)d_in[4];
    const float* Wk     = (const float*)d_in[5];
    const float* bk     = (const float*)d_in[6];
    const float* Wv     = (const float*)d_in[7];
    const float* bv     = (const float*)d_in[8];
    const float* Wo     = (const float*)d_in[9];
    const float* bo     = (const float*)d_in[10];
    float* out = (float*)d_out;

    __half *ah, *wh;
    cudaGetSymbolAddress((void**)&ah, g_ah);
    cudaGetSymbolAddress((void**)&wh, g_wh);

    static int smem_set = 0;
    if (!smem_set) {
        cudaFuncSetAttribute(gemm_qkv_kernel,
                             cudaFuncAttributeMaxDynamicSharedMemorySize, GEMM_SMEM);
        cudaFuncSetAttribute(gemm_wo_kernel,
                             cudaFuncAttributeMaxDynamicSharedMemorySize, GEMM_SMEM);
        cudaFuncSetAttribute(attn_hmma_kernel,
                             cudaFuncAttributeMaxDynamicSharedMemorySize, ATT_SMEM);
        smem_set = 1;
    }

    // ---- prep ----
    const int nA4 = NM * NE / 4;
    const int nW4 = EE / 4;
    tohalf_kernel<<<(nA4 + 255) / 256, 256>>>(hidden, ah, nA4);
    dim3 sgrid((nW4 + 255) / 256, 4);
    tohalf4_kernel<<<sgrid, 256>>>(Wq, Wk, Wv, Wo, wh, nW4);

    // ---- fused QKV projections (+RoPE, +V transpose) ----
    dim3 qkv_grid(33, (NM + 127) / 128);   // (33, 65)
    gemm_qkv_kernel<<<qkv_grid, 256, GEMM_SMEM>>>(bq, bk, bv, fcos, fsin);

    // ---- attention (BQ=96, 6 warps) ----
    dim3 attn_grid((NS + BQT - 1) / BQT, NH, NB);  // (11, 16, 8)
    attn_hmma_kernel<<<attn_grid, ATT_THREADS, ATT_SMEM>>>();

    // ---- output projection ----
    dim3 wo_grid(11, (NM + 127) / 128);
    gemm_wo_kernel<<<wo_grid, 256, GEMM_SMEM>>>(bo, out);
}